// round 13
// baseline (speedup 1.0000x reference)
#include <cuda_runtime.h>
#include <cuda_bf16.h>
#include <cstdint>

// ---------------------------------------------------------------------------
// Problem constants
// ---------------------------------------------------------------------------
#define NQ     75      // query images
#define NWAY   5
#define NC     640     // channels (K)
#define NHW    441     // descriptors per image
#define NSD    2205    // class descriptors per way (5 shots * 441)
#define MROWS  33075   // 75*441 packed query rows
#define MTILES 259     // ceil(33075/128)
#define MPAD   (MTILES * 128)   // 33152
#define SPAD   2304    // padded N per way (18 tiles of 128)
#define NT     18      // n-tiles of 128
#define BK     64      // k per chunk (int8 elements)
#define KCH    (NC / BK)        // 10 k-chunks per n-tile
#define TOTCH  (NT * KCH)       // 180 flattened chunks
#define SAS8   80      // smem row stride in BYTES (64 + 16 pad, conflict-free)

// smem layout (dynamic): 3-stage A ring | 3-stage B ring | merge
#define STG_BYTES (128 * SAS8)                 // 10240
#define SB_OFF    (3 * STG_BYTES)              // 30720
#define MERGE_OFF (6 * STG_BYTES)              // 61440
#define SMEM_TOTAL (MERGE_OFF + 128 * 2 * 3 * 4 + 64)   // ~64.6KB

// ---------------------------------------------------------------------------
// Scratch (device globals; no cudaMalloc allowed)
// ---------------------------------------------------------------------------
__device__ __align__(1024) int8_t d_q8[(size_t)MPAD * NC];
__device__ __align__(1024) int8_t d_s8[(size_t)NWAY * SPAD * NC];
__device__ float d_qs[MPAD];                 // per query-row dequant scale
__device__ float d_ss[NWAY * SPAD];          // per support-row dequant scale
__device__ float d_rowsum[(size_t)NWAY * MPAD];

// ---------------------------------------------------------------------------
// Helpers
// ---------------------------------------------------------------------------
__device__ __forceinline__ uint32_t smem_u32(const void* p) {
    uint32_t a;
    asm("{ .reg .u64 t; cvta.to.shared.u64 t, %1; cvt.u32.u64 %0, t; }"
        : "=r"(a) : "l"(p));
    return a;
}
__device__ __forceinline__ void cp16(uint32_t dst, const void* src) {
    asm volatile("cp.async.cg.shared.global [%0], [%1], 16;" :: "r"(dst), "l"(src));
}
#define CP_COMMIT() asm volatile("cp.async.commit_group;" ::: "memory")
#define CP_WAIT(n)  asm volatile("cp.async.wait_group %0;" :: "n"(n) : "memory")

__device__ __forceinline__ void ldsm_x4(uint32_t& r0, uint32_t& r1, uint32_t& r2,
                                        uint32_t& r3, uint32_t a) {
    asm volatile("ldmatrix.sync.aligned.m8n8.x4.shared.b16 {%0,%1,%2,%3}, [%4];"
                 : "=r"(r0), "=r"(r1), "=r"(r2), "=r"(r3) : "r"(a));
}
__device__ __forceinline__ void imma16832(int* c, uint32_t a0, uint32_t a1,
                                          uint32_t a2, uint32_t a3,
                                          uint32_t b0, uint32_t b1) {
    asm volatile(
        "mma.sync.aligned.m16n8k32.row.col.s32.s8.s8.s32 "
        "{%0,%1,%2,%3}, {%4,%5,%6,%7}, {%8,%9}, {%0,%1,%2,%3};"
        : "+r"(c[0]), "+r"(c[1]), "+r"(c[2]), "+r"(c[3])
        : "r"(a0), "r"(a1), "r"(a2), "r"(a3), "r"(b0), "r"(b1));
}
__device__ __forceinline__ void ins3(float v, float& a, float& b, float& c) {
    if (v > c) {
        if (v > a)      { c = b; b = a; a = v; }
        else if (v > b) { c = b; b = v; }
        else            { c = v; }
    }
}

// ---------------------------------------------------------------------------
// Kernel 0: zero int8 support scratch + padding scale entries.
// ---------------------------------------------------------------------------
__global__ void zero_kernel() {
    const size_t ns4 = sizeof(d_s8) / 16;
    uint4 z = make_uint4(0, 0, 0, 0);
    for (size_t i = (size_t)blockIdx.x * blockDim.x + threadIdx.x;
         i < ns4; i += (size_t)gridDim.x * blockDim.x)
        ((uint4*)d_s8)[i] = z;
    int t = blockIdx.x * blockDim.x + threadIdx.x;
    if (t < NWAY * SPAD) d_ss[t] = 0.f;
    if (t < MPAD - MROWS) d_qs[MROWS + t] = 0.f;
}

// ---------------------------------------------------------------------------
// Kernel 1: fused L2-normalize + transpose + per-row int8 quantization.
// One block per (image, 64-row m-slab).
//   q[m][c] = round( v * 127 / max_c|v| ),  scale[m] = max_c|v| * invnorm / 127
// ---------------------------------------------------------------------------
__global__ void __launch_bounds__(256) convert_kernel(const float* __restrict__ x1,
                                                      const float* __restrict__ x2) {
    int bid = blockIdx.x;
    const float* src;
    int8_t* dst;
    float* sdst;
    int m0;
    if (bid < 525) {
        int img = bid / 7; m0 = (bid % 7) * 64;
        src = x1 + (size_t)img * NC * NHW;
        dst = d_q8 + (size_t)img * NHW * NC;
        sdst = d_qs + (size_t)img * NHW;
    } else {
        int sid = bid - 525;
        int img = sid / 7; m0 = (sid % 7) * 64;
        int w = img / 5, sh = img % 5;
        src = x2 + (size_t)img * NC * NHW;
        dst = d_s8 + ((size_t)w * SPAD + (size_t)sh * NHW) * NC;
        sdst = d_ss + (size_t)w * SPAD + (size_t)sh * NHW;
    }
    int tid = threadIdx.x;
    int mx = tid & 63, cy = tid >> 6;

    __shared__ float sp[4][64];
    __shared__ float sm[4][64];
    __shared__ float sqm[64];        // 127 / amax
    __shared__ int8_t st[64][80];    // transposed tile, padded stride

    float acc = 0.f, amax = 0.f;
    if (m0 + mx < NHW) {
        for (int c = cy; c < NC; c += 4) {
            float v = src[(size_t)c * NHW + m0 + mx];
            acc = fmaf(v, v, acc);
            amax = fmaxf(amax, fabsf(v));
        }
    }
    sp[cy][mx] = acc;
    sm[cy][mx] = amax;
    __syncthreads();
    if (tid < 64) {
        float ss = sp[0][tid] + sp[1][tid] + sp[2][tid] + sp[3][tid];
        float mv = fmaxf(fmaxf(sm[0][tid], sm[1][tid]), fmaxf(sm[2][tid], sm[3][tid]));
        float inv = rsqrtf(fmaxf(ss, 1e-30f));
        sqm[tid] = (mv > 0.f) ? (127.f / mv) : 0.f;
        if (m0 + tid < NHW) sdst[m0 + tid] = mv * inv / 127.f;
    }
    __syncthreads();

    int mr = tid >> 2, qt = tid & 3;
    for (int c0 = 0; c0 < NC; c0 += 64) {
#pragma unroll
        for (int j = 0; j < 16; j++) {
            int idx = j * 256 + tid;
            int cl = idx >> 6, mm = idx & 63;
            float v = (m0 + mm < NHW) ? src[(size_t)(c0 + cl) * NHW + m0 + mm] : 0.f;
            int qv = __float2int_rn(v * sqm[mm]);
            qv = max(-127, min(127, qv));
            st[mm][cl] = (int8_t)qv;
        }
        __syncthreads();
        if (m0 + mr < NHW) {
            int8_t tmp[16];
#pragma unroll
            for (int i = 0; i < 16; i++) tmp[i] = st[mr][qt * 16 + i];
            int8_t* drow = dst + (size_t)(m0 + mr) * NC + c0 + qt * 16;
            *(uint4*)drow = *(uint4*)tmp;
        }
        __syncthreads();
    }
}

// ---------------------------------------------------------------------------
// Kernel 2: int8 mma.sync GEMM (s32 accum) + dequant + fused top-3 + row sum.
// CTA = (mtile, w). 128 threads = 2 warpM x 2 warpN, warp tile 64x64, BK=64.
// 180-chunk stream, 3-stage cp.async ring, one sync per chunk.
// Per chunk per warp: 16 LDSM + 64 IMMA (m16n8k32).
// ---------------------------------------------------------------------------
__global__ void __launch_bounds__(128, 2) sim_kernel() {
    extern __shared__ char smem[];
    const uint32_t sbA = smem_u32(smem);
    const uint32_t sbB = sbA + SB_OFF;
    float (*smerge)[2][3] = (float(*)[2][3])(smem + MERGE_OFF);

    const int bid   = blockIdx.x;
    const int w     = bid % NWAY;
    const int mtile = bid / NWAY;
    const int tid   = threadIdx.x;
    const int wid   = tid >> 5;
    const int lane  = tid & 31;
    const int warpM = wid & 1;
    const int warpN = wid >> 1;
    const int g8    = lane >> 2;
    const int tig   = lane & 3;

    const int8_t* Ab = d_q8 + (size_t)mtile * 128 * NC;
    const int8_t* Bw = d_s8 + (size_t)w * SPAD * NC;
    const float*  ssw = d_ss + (size_t)w * SPAD;

    // loader mapping: 512 16B-vectors per array per chunk; 4 per thread
    const int lrow = tid >> 2;              // 0..31, +32 per j
    const int lcb  = (tid & 3) * 16;        // byte col

    // ldmatrix byte coords
    const int arow = warpM * 64 + (lane & 15);
    const int acb  = (lane >> 4) * 16;
    const int brow = warpN * 64 + ((lane >> 4) << 3) + (lane & 7);  // + nh*16
    const int bcb  = ((lane >> 3) & 1) * 16;                         // + ks*32

    // per-slot query scales (rows fixed for this thread)
    float sq[8];
#pragma unroll
    for (int s = 0; s < 8; s++) {
        int row = mtile * 128 + warpM * 64 + (s >> 1) * 16 + (s & 1) * 8 + g8;
        sq[s] = d_qs[row];
    }

    float t0[8], t1[8], t2[8];
#pragma unroll
    for (int s = 0; s < 8; s++) { t0[s] = t1[s] = t2[s] = -1e30f; }

    int acc[4][8][4];   // [mf][nf][frag] s32

    auto issue = [&](int g2) {
        if (g2 < TOTCH) {
            int nt2 = g2 / KCH, kc2 = g2 - nt2 * KCH;
            uint32_t so = (uint32_t)(g2 % 3) * STG_BYTES;
            const int8_t* As = Ab + kc2 * BK;
            const int8_t* Bs = Bw + (size_t)nt2 * 128 * NC + kc2 * BK;
            uint32_t sdst = so + (uint32_t)(lrow * SAS8 + lcb);
            const int8_t* ag = As + (size_t)lrow * NC + lcb;
            const int8_t* bg = Bs + (size_t)lrow * NC + lcb;
#pragma unroll
            for (int j = 0; j < 4; j++) {
                cp16(sbA + sdst, ag);
                cp16(sbB + sdst, bg);
                sdst += 32 * SAS8;
                ag += 32 * NC;
                bg += 32 * NC;
            }
        }
        CP_COMMIT();
    };

    issue(0);
    issue(1);

    for (int g = 0; g < TOTCH; g++) {
        const int nt = g / KCH;
        const int kc = g - nt * KCH;
        const uint32_t cso = (uint32_t)(g % 3) * STG_BYTES;

        CP_WAIT(1);           // chunk g landed
        __syncthreads();      // everyone done with stage (g+2)%3
        issue(g + 2);

        if (kc == 0) {
#pragma unroll
            for (int mf = 0; mf < 4; mf++)
#pragma unroll
                for (int nf = 0; nf < 8; nf++)
#pragma unroll
                    for (int j = 0; j < 4; j++) acc[mf][nf][j] = 0;
        }

#pragma unroll
        for (int ks = 0; ks < 2; ks++) {        // k32 steps within 64-chunk
            uint32_t a0[4], a1[4], a2[4], a3[4];
#pragma unroll
            for (int mf = 0; mf < 4; mf++) {
                uint32_t addr = sbA + cso +
                    (uint32_t)((arow + mf * 16) * SAS8 + ks * 32 + acb);
                ldsm_x4(a0[mf], a1[mf], a2[mf], a3[mf], addr);
            }
            uint32_t b[8][2];
#pragma unroll
            for (int nh = 0; nh < 4; nh++) {
                uint32_t addr = sbB + cso +
                    (uint32_t)((brow + nh * 16) * SAS8 + ks * 32 + bcb);
                uint32_t r0, r1, r2, r3;
                ldsm_x4(r0, r1, r2, r3, addr);
                b[nh * 2][0] = r0;     b[nh * 2][1] = r1;
                b[nh * 2 + 1][0] = r2; b[nh * 2 + 1][1] = r3;
            }
#pragma unroll
            for (int mf = 0; mf < 4; mf++)
#pragma unroll
                for (int nf = 0; nf < 8; nf++)
                    imma16832(acc[mf][nf], a0[mf], a1[mf], a2[mf], a3[mf],
                              b[nf][0], b[nf][1]);
        }

        if (kc == KCH - 1) {
            // dequant + fold into running top-3 (mask N padding on last tile)
            const int climit = (nt == NT - 1) ? (NSD - (NT - 1) * 128) : 128;
#pragma unroll
            for (int nf = 0; nf < 8; nf++) {
                const int colb = warpN * 64 + nf * 8 + tig * 2;
                const bool u0 = colb < climit, u1 = colb + 1 < climit;
                const float ss0 = __ldg(&ssw[nt * 128 + colb]);
                const float ss1 = __ldg(&ssw[nt * 128 + colb + 1]);
#pragma unroll
                for (int mf = 0; mf < 4; mf++) {
                    const int s0 = mf * 2, s1 = mf * 2 + 1;
                    const int* c = acc[mf][nf];
                    if (u0) {
                        ins3((float)c[0] * sq[s0] * ss0, t0[s0], t1[s0], t2[s0]);
                        ins3((float)c[2] * sq[s1] * ss0, t0[s1], t1[s1], t2[s1]);
                    }
                    if (u1) {
                        ins3((float)c[1] * sq[s0] * ss1, t0[s0], t1[s0], t2[s0]);
                        ins3((float)c[3] * sq[s1] * ss1, t0[s1], t1[s1], t2[s1]);
                    }
                }
            }
        }
    }

    // intra-warp merge across the 4 lanes sharing each row
#pragma unroll
    for (int s = 0; s < 8; s++) {
#pragma unroll
        for (int d = 1; d <= 2; d <<= 1) {
            float m0 = __shfl_xor_sync(0xffffffffu, t0[s], d);
            float m1 = __shfl_xor_sync(0xffffffffu, t1[s], d);
            float m2 = __shfl_xor_sync(0xffffffffu, t2[s], d);
            ins3(m0, t0[s], t1[s], t2[s]);
            ins3(m1, t0[s], t1[s], t2[s]);
            ins3(m2, t0[s], t1[s], t2[s]);
        }
    }
    if (tig == 0) {
#pragma unroll
        for (int s = 0; s < 8; s++) {
            int row = warpM * 64 + (s >> 1) * 16 + (s & 1) * 8 + g8;
            smerge[row][warpN][0] = t0[s];
            smerge[row][warpN][1] = t1[s];
            smerge[row][warpN][2] = t2[s];
        }
    }
    __syncthreads();

    // merge the 2 N-warps per row; write per-row top-3 sum
    {
        int grow = mtile * 128 + tid;
        if (grow < MROWS) {
            float a = smerge[tid][0][0], b = smerge[tid][0][1], c = smerge[tid][0][2];
            ins3(smerge[tid][1][0], a, b, c);
            ins3(smerge[tid][1][1], a, b, c);
            d_rowsum[(size_t)w * MPAD + grow] = a + b + c + 0.f;
            // (full merge below)
            float aa = a, bb = b, cc = c;
            ins3(smerge[tid][1][2], aa, bb, cc);
            d_rowsum[(size_t)w * MPAD + grow] = aa + bb + cc;
        }
    }
}

// ---------------------------------------------------------------------------
// Kernel 3: one warp per (q, w) sums its 441 row contributions.
// ---------------------------------------------------------------------------
__global__ void reduce_kernel(float* __restrict__ out) {
    int wi = (blockIdx.x * blockDim.x + threadIdx.x) >> 5;
    int lane = threadIdx.x & 31;
    if (wi >= NQ * NWAY) return;
    int q = wi / NWAY, w = wi % NWAY;
    const float* rs = d_rowsum + (size_t)w * MPAD + (size_t)q * NHW;
    float s = 0.f;
    for (int m = lane; m < NHW; m += 32) s += rs[m];
#pragma unroll
    for (int o = 16; o > 0; o >>= 1) s += __shfl_xor_sync(0xffffffffu, s, o);
    if (lane == 0) out[wi] = s;
}

// ---------------------------------------------------------------------------
extern "C" void kernel_launch(void* const* d_in, const int* in_sizes, int n_in,
                              void* d_out, int out_size) {
    const float* x1 = (const float*)d_in[0];   // [75, 640, 21, 21]
    const float* x2 = (const float*)d_in[1];   // [25, 640, 21, 21]
    float* out = (float*)d_out;                // [75, 5]

    cudaFuncSetAttribute(sim_kernel, cudaFuncAttributeMaxDynamicSharedMemorySize,
                         SMEM_TOTAL);

    zero_kernel<<<512, 256>>>();
    convert_kernel<<<700, 256>>>(x1, x2);
    sim_kernel<<<MTILES * NWAY, 128, SMEM_TOTAL>>>();
    reduce_kernel<<<(NQ * NWAY * 32 + 255) / 256, 256>>>(out);
}

// round 14
// speedup vs baseline: 2.2382x; 2.2382x over previous
#include <cuda_runtime.h>
#include <cuda_bf16.h>
#include <cstdint>

// ---------------------------------------------------------------------------
// Problem constants
// ---------------------------------------------------------------------------
#define NQ     75      // query images
#define NWAY   5
#define NC     640     // channels (K)
#define NHW    441     // descriptors per image
#define NSD    2205    // class descriptors per way (5 shots * 441)
#define MROWS  33075   // 75*441 packed query rows
#define MTILES 259     // ceil(33075/128)
#define MPAD   (MTILES * 128)   // 33152
#define SPAD   2304    // padded N per way (18 tiles of 128)
#define NT     18      // n-tiles of 128 total
#define NTH    9       // n-tiles per CTA (half split)
#define BK     64
#define KCH    (NC / BK)        // 10 k-chunks per n-tile
#define TOTCH  (NTH * KCH)      // 90 flattened chunks per CTA
#define SAS    72      // smem row stride in bf16 (64 + 8 pad, conflict-free ldmatrix)

// smem layout (dynamic): 3-stage A ring | 3-stage B ring | merge
#define STG_BYTES (128 * SAS * 2)              // 18432
#define SB_OFF    (3 * STG_BYTES)              // 55296
#define MERGE_OFF (6 * STG_BYTES)              // 110592
#define SMEM_TOTAL (MERGE_OFF + 128 * 2 * 3 * 4 + 64)   // 113728 (~111KB)

// ---------------------------------------------------------------------------
// Scratch (device globals; no cudaMalloc allowed)
// ---------------------------------------------------------------------------
__device__ __align__(1024) __nv_bfloat16 d_q[(size_t)MPAD * NC];
__device__ __align__(1024) __nv_bfloat16 d_s[(size_t)NWAY * SPAD * NC];
__device__ float d_top3[(size_t)NWAY * 2 * MPAD * 3];   // per (w, half, row) top-3

// ---------------------------------------------------------------------------
// Helpers
// ---------------------------------------------------------------------------
__device__ __forceinline__ uint32_t smem_u32(const void* p) {
    uint32_t a;
    asm("{ .reg .u64 t; cvta.to.shared.u64 t, %1; cvt.u32.u64 %0, t; }"
        : "=r"(a) : "l"(p));
    return a;
}
__device__ __forceinline__ void cp16(uint32_t dst, const void* src) {
    asm volatile("cp.async.cg.shared.global [%0], [%1], 16;" :: "r"(dst), "l"(src));
}
#define CP_COMMIT() asm volatile("cp.async.commit_group;" ::: "memory")
#define CP_WAIT(n)  asm volatile("cp.async.wait_group %0;" :: "n"(n) : "memory")

__device__ __forceinline__ void ldsm_x4(uint32_t& r0, uint32_t& r1, uint32_t& r2,
                                        uint32_t& r3, uint32_t a) {
    asm volatile("ldmatrix.sync.aligned.m8n8.x4.shared.b16 {%0,%1,%2,%3}, [%4];"
                 : "=r"(r0), "=r"(r1), "=r"(r2), "=r"(r3) : "r"(a));
}
__device__ __forceinline__ void mma16816(float* c, uint32_t a0, uint32_t a1,
                                         uint32_t a2, uint32_t a3,
                                         uint32_t b0, uint32_t b1) {
    asm volatile(
        "mma.sync.aligned.m16n8k16.row.col.f32.bf16.bf16.f32 "
        "{%0,%1,%2,%3}, {%4,%5,%6,%7}, {%8,%9}, {%0,%1,%2,%3};"
        : "+f"(c[0]), "+f"(c[1]), "+f"(c[2]), "+f"(c[3])
        : "r"(a0), "r"(a1), "r"(a2), "r"(a3), "r"(b0), "r"(b1));
}
__device__ __forceinline__ void ins3(float v, float& a, float& b, float& c) {
    if (v > c) {
        if (v > a)      { c = b; b = a; a = v; }
        else if (v > b) { c = b; b = v; }
        else            { c = v; }
    }
}

// ---------------------------------------------------------------------------
// Kernel 1: fused L2-normalize + transpose [C,HW]->[HW,C] + bf16 convert.
// (No zero kernel: padded B columns / A tail rows are masked downstream.)
// ---------------------------------------------------------------------------
__global__ void __launch_bounds__(256) convert_kernel(const float* __restrict__ x1,
                                                      const float* __restrict__ x2) {
    int bid = blockIdx.x;
    const float* src;
    __nv_bfloat16* dst;
    int m0;
    if (bid < 525) {
        int img = bid / 7; m0 = (bid % 7) * 64;
        src = x1 + (size_t)img * NC * NHW;
        dst = d_q + (size_t)img * NHW * NC;          // packed, no per-image pad
    } else {
        int sid = bid - 525;
        int img = sid / 7; m0 = (sid % 7) * 64;
        int w = img / 5, sh = img % 5;
        src = x2 + (size_t)img * NC * NHW;
        dst = d_s + ((size_t)w * SPAD + (size_t)sh * NHW) * NC;
    }
    int tid = threadIdx.x;
    int mx = tid & 63, cy = tid >> 6;

    __shared__ float sp[4][64];
    __shared__ float sinv[64];
    __shared__ __nv_bfloat16 st[64][72];

    float acc = 0.f;
    if (m0 + mx < NHW) {
        for (int c = cy; c < NC; c += 4) {
            float v = src[(size_t)c * NHW + m0 + mx];
            acc = fmaf(v, v, acc);
        }
    }
    sp[cy][mx] = acc;
    __syncthreads();
    if (tid < 64)
        sinv[tid] = rsqrtf(sp[0][tid] + sp[1][tid] + sp[2][tid] + sp[3][tid]);
    __syncthreads();

    int mr = tid >> 2, qt = tid & 3;
    for (int c0 = 0; c0 < NC; c0 += 64) {
#pragma unroll
        for (int j = 0; j < 16; j++) {
            int idx = j * 256 + tid;
            int cl = idx >> 6, mm = idx & 63;
            float v = (m0 + mm < NHW) ? src[(size_t)(c0 + cl) * NHW + m0 + mm] : 0.f;
            st[mm][cl] = __float2bfloat16(v * sinv[mm]);
        }
        __syncthreads();
        if (m0 + mr < NHW) {
            __nv_bfloat16 tmp[16];
#pragma unroll
            for (int i = 0; i < 16; i++) tmp[i] = st[mr][qt * 16 + i];
            __nv_bfloat16* drow = dst + (size_t)(m0 + mr) * NC + c0 + qt * 16;
            ((uint4*)drow)[0] = ((uint4*)tmp)[0];
            ((uint4*)drow)[1] = ((uint4*)tmp)[1];
        }
        __syncthreads();
    }
}

// ---------------------------------------------------------------------------
// Kernel 2: bf16 mma.sync GEMM + fused top-3.
// CTA = (mtile, w, nhalf). 128 threads = 2 warpM x 2 warpN, warp tile 64x64.
// Each CTA covers 9 n-tiles (half the N range): 90-chunk stream, 3-stage
// cp.async ring, one sync per chunk. Emits per-row top-3 for its half.
// Grid 2590 -> 97% wave utilization at 2 CTAs/SM (vs 87.5% unsplit).
// ---------------------------------------------------------------------------
__global__ void __launch_bounds__(128, 2) sim_kernel() {
    extern __shared__ char smem[];
    const uint32_t sbA = smem_u32(smem);
    const uint32_t sbB = sbA + SB_OFF;
    float (*smerge)[2][3] = (float(*)[2][3])(smem + MERGE_OFF);

    const int bid   = blockIdx.x;
    const int half  = bid & 1;
    const int rest  = bid >> 1;
    const int w     = rest % NWAY;
    const int mtile = rest / NWAY;
    const int tid   = threadIdx.x;
    const int wid   = tid >> 5;
    const int lane  = tid & 31;
    const int warpM = wid & 1;
    const int warpN = wid >> 1;
    const int g8    = lane >> 2;
    const int tig   = lane & 3;

    const __nv_bfloat16* Ab = d_q + (size_t)mtile * 128 * NC;
    const __nv_bfloat16* Bw = d_s + ((size_t)w * SPAD + (size_t)half * NTH * 128) * NC;

    // loader mapping: 1024 16B-vectors per array per chunk; 8 per thread per array
    const int lrow0 = tid >> 3;            // 0..15, step 16 per j
    const int lc8   = (tid & 7) * 8;       // col in bf16

    // ldmatrix coords
    const int arow = warpM * 64 + (lane & 15);
    const int acol = (lane >> 4) * 8;
    const int brow = warpN * 64 + ((lane >> 4) << 3) + (lane & 7);  // + nh*16
    const int bcol = ((lane >> 3) & 1) * 8;                          // + ks*16

    float t0[8], t1[8], t2[8];
#pragma unroll
    for (int s = 0; s < 8; s++) { t0[s] = t1[s] = t2[s] = -1e30f; }

    float acc[4][8][4];   // [mf][nf][frag]

    auto issue = [&](int g2) {
        if (g2 < TOTCH) {
            int nt2 = g2 / KCH, kc2 = g2 - nt2 * KCH;
            uint32_t so = (uint32_t)(g2 % 3) * STG_BYTES;
            const __nv_bfloat16* As = Ab + kc2 * BK;
            const __nv_bfloat16* Bs = Bw + (size_t)nt2 * 128 * NC + kc2 * BK;
            uint32_t sdst = so + (uint32_t)(lrow0 * SAS + lc8) * 2;
            const __nv_bfloat16* ag = As + (size_t)lrow0 * NC + lc8;
            const __nv_bfloat16* bg = Bs + (size_t)lrow0 * NC + lc8;
#pragma unroll
            for (int j = 0; j < 8; j++) {
                cp16(sbA + sdst, ag);
                cp16(sbB + sdst, bg);
                sdst += 16 * SAS * 2;
                ag += 16 * NC;
                bg += 16 * NC;
            }
        }
        CP_COMMIT();
    };

    issue(0);
    issue(1);

    for (int g = 0; g < TOTCH; g++) {
        const int ntl = g / KCH;               // local n-tile 0..8
        const int kc  = g - ntl * KCH;
        const uint32_t cso = (uint32_t)(g % 3) * STG_BYTES;

        CP_WAIT(1);           // chunk g landed
        __syncthreads();      // everyone done with stage (g+2)%3
        issue(g + 2);

        if (kc == 0) {
#pragma unroll
            for (int mf = 0; mf < 4; mf++)
#pragma unroll
                for (int nf = 0; nf < 8; nf++)
#pragma unroll
                    for (int j = 0; j < 4; j++) acc[mf][nf][j] = 0.f;
        }

#pragma unroll
        for (int ks = 0; ks < 4; ks++) {
            uint32_t a0[4], a1[4], a2[4], a3[4];
#pragma unroll
            for (int mf = 0; mf < 4; mf++) {
                uint32_t addr = sbA + cso +
                    (uint32_t)((arow + mf * 16) * SAS + ks * 16 + acol) * 2;
                ldsm_x4(a0[mf], a1[mf], a2[mf], a3[mf], addr);
            }
            uint32_t b[8][2];
#pragma unroll
            for (int nh = 0; nh < 4; nh++) {
                uint32_t addr = sbB + cso +
                    (uint32_t)((brow + nh * 16) * SAS + ks * 16 + bcol) * 2;
                uint32_t r0, r1, r2, r3;
                ldsm_x4(r0, r1, r2, r3, addr);
                b[nh * 2][0] = r0;     b[nh * 2][1] = r1;
                b[nh * 2 + 1][0] = r2; b[nh * 2 + 1][1] = r3;
            }
#pragma unroll
            for (int mf = 0; mf < 4; mf++)
#pragma unroll
                for (int nf = 0; nf < 8; nf++)
                    mma16816(acc[mf][nf], a0[mf], a1[mf], a2[mf], a3[mf],
                             b[nf][0], b[nf][1]);
        }

        if (kc == KCH - 1) {
            // fold this n-tile into running top-3 (mask N padding on last tile)
            const int ntg = half * NTH + ntl;  // global n-tile
            const int climit = (ntg == NT - 1) ? (NSD - (NT - 1) * 128) : 128;
#pragma unroll
            for (int mf = 0; mf < 4; mf++) {
                const int s0 = mf * 2, s1 = mf * 2 + 1;
#pragma unroll
                for (int nf = 0; nf < 8; nf++) {
                    const int colb = warpN * 64 + nf * 8 + tig * 2;
                    const bool u0 = colb < climit, u1 = colb + 1 < climit;
                    const float* c = acc[mf][nf];
                    if (u0) { ins3(c[0], t0[s0], t1[s0], t2[s0]);
                              ins3(c[2], t0[s1], t1[s1], t2[s1]); }
                    if (u1) { ins3(c[1], t0[s0], t1[s0], t2[s0]);
                              ins3(c[3], t0[s1], t1[s1], t2[s1]); }
                }
            }
        }
    }

    // intra-warp merge across the 4 lanes sharing each row
#pragma unroll
    for (int s = 0; s < 8; s++) {
#pragma unroll
        for (int d = 1; d <= 2; d <<= 1) {
            float m0 = __shfl_xor_sync(0xffffffffu, t0[s], d);
            float m1 = __shfl_xor_sync(0xffffffffu, t1[s], d);
            float m2 = __shfl_xor_sync(0xffffffffu, t2[s], d);
            ins3(m0, t0[s], t1[s], t2[s]);
            ins3(m1, t0[s], t1[s], t2[s]);
            ins3(m2, t0[s], t1[s], t2[s]);
        }
    }
    if (tig == 0) {
#pragma unroll
        for (int s = 0; s < 8; s++) {
            int row = warpM * 64 + (s >> 1) * 16 + (s & 1) * 8 + g8;
            smerge[row][warpN][0] = t0[s];
            smerge[row][warpN][1] = t1[s];
            smerge[row][warpN][2] = t2[s];
        }
    }
    __syncthreads();

    // merge the 2 N-warps per row; write per-row top-3 for this half
    {
        int grow = mtile * 128 + tid;
        if (grow < MROWS) {
            float a = smerge[tid][0][0], b = smerge[tid][0][1], c = smerge[tid][0][2];
            ins3(smerge[tid][1][0], a, b, c);
            ins3(smerge[tid][1][1], a, b, c);
            ins3(smerge[tid][1][2], a, b, c);
            float* dst = d_top3 + ((size_t)(w * 2 + half) * MPAD + grow) * 3;
            dst[0] = a; dst[1] = b; dst[2] = c;
        }
    }
}

// ---------------------------------------------------------------------------
// Kernel 3: one warp per (q, w): merge the two halves' top-3 per row, sum.
// ---------------------------------------------------------------------------
__global__ void reduce_kernel(float* __restrict__ out) {
    int wi = (blockIdx.x * blockDim.x + threadIdx.x) >> 5;
    int lane = threadIdx.x & 31;
    if (wi >= NQ * NWAY) return;
    int q = wi / NWAY, w = wi % NWAY;
    const float* h0 = d_top3 + ((size_t)(w * 2 + 0) * MPAD + (size_t)q * NHW) * 3;
    const float* h1 = d_top3 + ((size_t)(w * 2 + 1) * MPAD + (size_t)q * NHW) * 3;
    float s = 0.f;
    for (int m = lane; m < NHW; m += 32) {
        float a = h0[m * 3], b = h0[m * 3 + 1], c = h0[m * 3 + 2];
        ins3(h1[m * 3],     a, b, c);
        ins3(h1[m * 3 + 1], a, b, c);
        ins3(h1[m * 3 + 2], a, b, c);
        s += a + b + c;
    }
#pragma unroll
    for (int o = 16; o > 0; o >>= 1) s += __shfl_xor_sync(0xffffffffu, s, o);
    if (lane == 0) out[wi] = s;
}

// ---------------------------------------------------------------------------
extern "C" void kernel_launch(void* const* d_in, const int* in_sizes, int n_in,
                              void* d_out, int out_size) {
    const float* x1 = (const float*)d_in[0];   // [75, 640, 21, 21]
    const float* x2 = (const float*)d_in[1];   // [25, 640, 21, 21]
    float* out = (float*)d_out;                // [75, 5]

    cudaFuncSetAttribute(sim_kernel, cudaFuncAttributeMaxDynamicSharedMemorySize,
                         SMEM_TOTAL);

    convert_kernel<<<700, 256>>>(x1, x2);
    sim_kernel<<<MTILES * NWAY * 2, 128, SMEM_TOTAL>>>();
    reduce_kernel<<<(NQ * NWAY * 32 + 255) / 256, 256>>>(out);
}